// round 17
// baseline (speedup 1.0000x reference)
#include <cuda_runtime.h>
#include <cuda_bf16.h>
#include <cuda_fp16.h>
#include <cstdint>

#define N_TOK 49
#define C_DIM 96
#define RS 80            // row stride bytes (64B data + 16B pad)
#define HEAD_SM 15360    // per-head smem: q@0, k@5120, v@10240
#define SMEM_BYTES 46080

__device__ __half g_bias4h[3 * 4 * 7 * 32 * 4];  // C-fragment-ordered, fp16

// ---------------------------------------------------------------------------
__device__ __forceinline__ uint32_t smem_u32(const void* p) {
    uint32_t a;
    asm("{ .reg .u64 t; cvta.to.shared.u64 t, %1; cvt.u32.u64 %0, t; }" : "=r"(a) : "l"(p));
    return a;
}
__device__ __forceinline__ void ldsm4(uint32_t r[4], uint32_t addr) {
    asm volatile("ldmatrix.sync.aligned.m8n8.x4.shared.b16 {%0,%1,%2,%3}, [%4];"
                 : "=r"(r[0]), "=r"(r[1]), "=r"(r[2]), "=r"(r[3]) : "r"(addr));
}
__device__ __forceinline__ void ldsm4t(uint32_t r[4], uint32_t addr) {
    asm volatile("ldmatrix.sync.aligned.m8n8.x4.trans.shared.b16 {%0,%1,%2,%3}, [%4];"
                 : "=r"(r[0]), "=r"(r[1]), "=r"(r[2]), "=r"(r[3]) : "r"(addr));
}
__device__ __forceinline__ void mma16816h(float c[4], const uint32_t a0, const uint32_t a1,
                                          const uint32_t a2, const uint32_t a3,
                                          uint32_t b0, uint32_t b1) {
    asm volatile(
        "mma.sync.aligned.m16n8k16.row.col.f32.f16.f16.f32 "
        "{%0,%1,%2,%3}, {%4,%5,%6,%7}, {%8,%9}, {%0,%1,%2,%3};"
        : "+f"(c[0]), "+f"(c[1]), "+f"(c[2]), "+f"(c[3])
        : "r"(a0), "r"(a1), "r"(a2), "r"(a3), "r"(b0), "r"(b1));
}
__device__ __forceinline__ uint32_t pkh2(float x, float y) {
    __half2 h = __floats2half2_rn(x, y);
    return *reinterpret_cast<uint32_t*>(&h);
}

// ---------------------------------------------------------------------------
// Bias MLP, slice-parallel (8 lanes per position), writing DIRECTLY into the
// C-fragment-ordered fp16 table g_bias4h. -1e30 -> -inf in fp16 (mask OK).
// ---------------------------------------------------------------------------
__global__ void bias_kernel(const float* __restrict__ rel_pos,
                            const float* __restrict__ w1,
                            const float* __restrict__ b1,
                            const float* __restrict__ w2,
                            const float* __restrict__ b2) {
    int gid = blockIdx.x * blockDim.x + threadIdx.x;
    if (gid >= 64 * 56 * 8) return;
    const int s = gid & 7;          // hidden-slice index
    const int p = gid >> 3;         // position [0, 3584)
    const int n = p / 56;
    const int m = p - n * 56;

    float a0 = 0.f, a1 = 0.f, a2 = 0.f;
    const bool live = (n < N_TOK) && (m < N_TOK);
    if (live) {
        const int idx = n * N_TOK + m;
        const float r0 = rel_pos[2 * idx + 0];
        const float r1 = rel_pos[2 * idx + 1];
        const int j0 = s * 32;
        #pragma unroll 8
        for (int j = j0; j < j0 + 32; ++j) {
            float hj = fmaf(r0, __ldg(w1 + j), fmaf(r1, __ldg(w1 + 256 + j), __ldg(b1 + j)));
            hj = fmaxf(hj, 0.0f);
            a0 = fmaf(hj, __ldg(w2 + j * 3 + 0), a0);
            a1 = fmaf(hj, __ldg(w2 + j * 3 + 1), a1);
            a2 = fmaf(hj, __ldg(w2 + j * 3 + 2), a2);
        }
    }
    #pragma unroll
    for (int o = 1; o < 8; o <<= 1) {
        a0 += __shfl_xor_sync(0xffffffffu, a0, o);
        a1 += __shfl_xor_sync(0xffffffffu, a1, o);
        a2 += __shfl_xor_sync(0xffffffffu, a2, o);
    }
    if (s == 0) {
        float v0, v1, v2;
        if (m >= N_TOK)      { v0 = v1 = v2 = -1e30f; }   // -> -inf in fp16
        else if (n >= N_TOK) { v0 = v1 = v2 = 0.0f; }
        else { v0 = a0 + __ldg(b2 + 0); v1 = a1 + __ldg(b2 + 1); v2 = a2 + __ldg(b2 + 2); }
        const int w    = n >> 4;
        const int half = (n >> 3) & 1;
        const int g    = n & 7;
        const int j    = m >> 3;
        const int tig  = (m & 7) >> 1;
        const int comp = m & 1;
        const int lane4 = g * 4 + tig;
        const int fi    = half * 2 + comp;
        __half* base = g_bias4h + fi;
        base[(((0 * 4 + w) * 7 + j) * 32 + lane4) * 4] = __float2half(v0);
        base[(((1 * 4 + w) * 7 + j) * 32 + lane4) * 4] = __float2half(v1);
        base[(((2 * 4 + w) * 7 + j) * 32 + lane4) * 4] = __float2half(v2);
    }
}

// ---------------------------------------------------------------------------
// CTA = window, 6 warps (192 thr). warp -> (head h = w>>1, half = w&1),
// owning rows [half*32, half*32+32) = 2 m16 tiles. k/v fragments are loaded
// once per warp and shared across both tiles (2x less ldsm redundancy than
// the 4-warp (window,head) layout). QK/PV single fp16; bias fp16 table init.
// j=7 all-pad column block skipped.
// ---------------------------------------------------------------------------
__global__ __launch_bounds__(192, 4)
void attn_kernel(const float* __restrict__ q,
                 const float* __restrict__ k,
                 const float* __restrict__ v,
                 float*       __restrict__ out) {
    __shared__ __align__(16) char S[SMEM_BYTES];
    const uint32_t sb = smem_u32(S);

    const int tid  = threadIdx.x;
    const int lane = tid & 31;
    const int warp = tid >> 5;          // 0..5
    const int g    = lane >> 2;
    const int tig  = lane & 3;
    const int h    = warp >> 1;         // head 0..2
    const int half = warp & 1;          // 32-row half
    const int POFF = (lane & 7) + 8 * ((lane >> 3) & 1);
    const int CG   = lane >> 4;
    const size_t wbase = (size_t)blockIdx.x * (N_TOK * C_DIM);

    // ---- stage q (scaled), k, v for ALL 3 heads as single fp16 ----
    {
        const float SC = 0.17677669529663687f;  // 1/sqrt(32)
        #pragma unroll
        for (int it = 0; it < 8; ++it) {
            int i = tid + it * 192;            // 1536 = 3 heads x 64 rows x 8 chunks
            int hh  = i >> 9;
            int rem = i & 511;
            int n = rem >> 3, c = rem & 7;
            uint32_t off = (uint32_t)(hh * HEAD_SM + n * RS + c * 8);
            uint2 qh2 = make_uint2(0, 0), kh2 = qh2, vh2 = qh2;
            if (n < N_TOK) {
                size_t ga = wbase + (size_t)n * C_DIM + hh * 32 + c * 4;
                float4 xq = *(const float4*)(q + ga);
                float4 xk = *(const float4*)(k + ga);
                float4 xv = *(const float4*)(v + ga);
                qh2.x = pkh2(xq.x * SC, xq.y * SC);
                qh2.y = pkh2(xq.z * SC, xq.w * SC);
                kh2.x = pkh2(xk.x, xk.y);
                kh2.y = pkh2(xk.z, xk.w);
                vh2.x = pkh2(xv.x, xv.y);
                vh2.y = pkh2(xv.z, xv.w);
            }
            *(uint2*)(S + off)         = qh2;
            *(uint2*)(S + 5120 + off)  = kh2;
            *(uint2*)(S + 10240 + off) = vh2;
        }
    }

    // ---- bias -> accumulator init (fp16 fragment-ordered table) ----
    float acc[2][7][4];
    #pragma unroll
    for (int t2 = 0; t2 < 2; ++t2) {
        const uint2* bt = (const uint2*)g_bias4h +
                          ((h * 4 + (half * 2 + t2)) * 7) * 32 + lane;
        #pragma unroll
        for (int j = 0; j < 7; ++j) {
            uint2 bv = __ldg(bt + j * 32);
            float2 f01 = __half22float2(*reinterpret_cast<__half2*>(&bv.x));
            float2 f23 = __half22float2(*reinterpret_cast<__half2*>(&bv.y));
            acc[t2][j][0] = f01.x;  acc[t2][j][1] = f01.y;
            acc[t2][j][2] = f23.x;  acc[t2][j][3] = f23.y;
        }
    }
    __syncthreads();

    const uint32_t hbase = sb + h * HEAD_SM;

    // ---- q A-fragments via ldmatrix (2 m16 tiles) ----
    uint32_t qf[2][2][4];
    #pragma unroll
    for (int t2 = 0; t2 < 2; ++t2) {
        const uint32_t aP = hbase +
            (uint32_t)((half * 32 + t2 * 16 + POFF) * RS + CG * 16);
        ldsm4(qf[t2][0], aP);
        ldsm4(qf[t2][1], aP + 32);
    }

    // ---- QK: bias + q_f16 @ k_f16^T;  k frags shared across tiles ----
    {
        const uint32_t kP = hbase + 5120 +
            (uint32_t)((lane & 7) * RS + (lane >> 3) * 16);
        #pragma unroll
        for (int j = 0; j < 7; ++j) {
            uint32_t bh[4];
            ldsm4(bh, kP + (uint32_t)(j * 8 * RS));
            #pragma unroll
            for (int t2 = 0; t2 < 2; ++t2) {
                mma16816h(acc[t2][j], qf[t2][0][0], qf[t2][0][1], qf[t2][0][2], qf[t2][0][3],
                          bh[0], bh[1]);
                mma16816h(acc[t2][j], qf[t2][1][0], qf[t2][1][1], qf[t2][1][2], qf[t2][1][3],
                          bh[2], bh[3]);
            }
        }
    }

    // ---- softmax in-place per tile (rows n1, n2; quad-local reductions) ----
    float rinv1[2], rinv2[2];
    #pragma unroll
    for (int t2 = 0; t2 < 2; ++t2) {
        float mx1 = acc[t2][0][0], mx2 = acc[t2][0][2];
        #pragma unroll
        for (int j = 0; j < 7; ++j) {
            mx1 = fmaxf(mx1, fmaxf(acc[t2][j][0], acc[t2][j][1]));
            mx2 = fmaxf(mx2, fmaxf(acc[t2][j][2], acc[t2][j][3]));
        }
        mx1 = fmaxf(mx1, __shfl_xor_sync(0xffffffffu, mx1, 1));
        mx1 = fmaxf(mx1, __shfl_xor_sync(0xffffffffu, mx1, 2));
        mx2 = fmaxf(mx2, __shfl_xor_sync(0xffffffffu, mx2, 1));
        mx2 = fmaxf(mx2, __shfl_xor_sync(0xffffffffu, mx2, 2));
        float sum1 = 0.0f, sum2 = 0.0f;
        #pragma unroll
        for (int j = 0; j < 7; ++j) {
            acc[t2][j][0] = __expf(acc[t2][j][0] - mx1); sum1 += acc[t2][j][0];
            acc[t2][j][1] = __expf(acc[t2][j][1] - mx1); sum1 += acc[t2][j][1];
            acc[t2][j][2] = __expf(acc[t2][j][2] - mx2); sum2 += acc[t2][j][2];
            acc[t2][j][3] = __expf(acc[t2][j][3] - mx2); sum2 += acc[t2][j][3];
        }
        sum1 += __shfl_xor_sync(0xffffffffu, sum1, 1);
        sum1 += __shfl_xor_sync(0xffffffffu, sum1, 2);
        sum2 += __shfl_xor_sync(0xffffffffu, sum2, 1);
        sum2 += __shfl_xor_sync(0xffffffffu, sum2, 2);
        rinv1[t2] = 1.0f / sum1;
        rinv2[t2] = 1.0f / sum2;
    }

    // ---- e A-fragments: single fp16 (cols 56..63 -> 0) ----
    uint32_t eh[2][4][4];
    #pragma unroll
    for (int t2 = 0; t2 < 2; ++t2) {
        #pragma unroll
        for (int t = 0; t < 3; ++t) {
            eh[t2][t][0] = pkh2(acc[t2][2*t][0],   acc[t2][2*t][1]);
            eh[t2][t][1] = pkh2(acc[t2][2*t][2],   acc[t2][2*t][3]);
            eh[t2][t][2] = pkh2(acc[t2][2*t+1][0], acc[t2][2*t+1][1]);
            eh[t2][t][3] = pkh2(acc[t2][2*t+1][2], acc[t2][2*t+1][3]);
        }
        eh[t2][3][0] = pkh2(acc[t2][6][0], acc[t2][6][1]);
        eh[t2][3][1] = pkh2(acc[t2][6][2], acc[t2][6][3]);
        eh[t2][3][2] = 0u;
        eh[t2][3][3] = 0u;
    }

    // ---- PV: O = e_f16 @ v_f16;  v frags shared across tiles ----
    float o[2][4][4];
    #pragma unroll
    for (int t2 = 0; t2 < 2; ++t2)
        #pragma unroll
        for (int j = 0; j < 4; ++j)
            #pragma unroll
            for (int c = 0; c < 4; ++c) o[t2][j][c] = 0.0f;

    {
        const uint32_t vP = hbase + 10240 + (uint32_t)(POFF * RS + CG * 16);
        #pragma unroll
        for (int t = 0; t < 4; ++t) {
            uint32_t va[4], vb[4];
            const uint32_t base = vP + (uint32_t)(t * 16 * RS);
            ldsm4t(va, base);
            ldsm4t(vb, base + 32);
            #pragma unroll
            for (int t2 = 0; t2 < 2; ++t2) {
                mma16816h(o[t2][0], eh[t2][t][0], eh[t2][t][1], eh[t2][t][2], eh[t2][t][3],
                          va[0], va[1]);
                mma16816h(o[t2][1], eh[t2][t][0], eh[t2][t][1], eh[t2][t][2], eh[t2][t][3],
                          va[2], va[3]);
                mma16816h(o[t2][2], eh[t2][t][0], eh[t2][t][1], eh[t2][t][2], eh[t2][t][3],
                          vb[0], vb[1]);
                mma16816h(o[t2][3], eh[t2][t][0], eh[t2][t][1], eh[t2][t][2], eh[t2][t][3],
                          vb[2], vb[3]);
            }
        }
    }

    // ---- normalize + store ----
    #pragma unroll
    for (int t2 = 0; t2 < 2; ++t2) {
        const int n1 = half * 32 + t2 * 16 + g;
        const int n2 = n1 + 8;
        if (n1 < N_TOK) {
            float* op = out + wbase + (size_t)n1 * C_DIM + h * 32;
            #pragma unroll
            for (int j = 0; j < 4; ++j)
                *(float2*)(op + 8 * j + 2 * tig) =
                    make_float2(o[t2][j][0] * rinv1[t2], o[t2][j][1] * rinv1[t2]);
        }
        if (n2 < N_TOK) {
            float* op = out + wbase + (size_t)n2 * C_DIM + h * 32;
            #pragma unroll
            for (int j = 0; j < 4; ++j)
                *(float2*)(op + 8 * j + 2 * tig) =
                    make_float2(o[t2][j][2] * rinv2[t2], o[t2][j][3] * rinv2[t2]);
        }
    }
}

// ---------------------------------------------------------------------------
extern "C" void kernel_launch(void* const* d_in, const int* in_sizes, int n_in,
                              void* d_out, int out_size) {
    const float* q       = (const float*)d_in[0];
    const float* k       = (const float*)d_in[1];
    const float* v       = (const float*)d_in[2];
    const float* rel_pos = (const float*)d_in[3];
    const float* w1      = (const float*)d_in[4];
    const float* b1      = (const float*)d_in[5];
    const float* w2      = (const float*)d_in[6];
    const float* b2      = (const float*)d_in[7];
    float* out = (float*)d_out;

    const int nwin = in_sizes[0] / (N_TOK * C_DIM);

    bias_kernel<<<(64 * 56 * 8 + 127) / 128, 128>>>(rel_pos, w1, b1, w2, b2);
    attn_kernel<<<nwin, 192>>>(q, k, v, out);
}